// round 16
// baseline (speedup 1.0000x reference)
#include <cuda_runtime.h>

// PyramidROIAlign: B=2, N=1000 boxes, C=256, 7x7 pool. Single fused kernel.
// R12 champion structure (128-thread CTA = 8 items, guarded param phase ->
// barrier -> 16-lanes/item unroll-4 gather, regs pinned, __stcs stores) with
// scalar weight-form lerp: 4 precomputed bilinear weights, 16 FFMA per float4
// (vs 24 FADD/FFMA in the reference-shaped lerp). All-32-bit registers.

#define POOL 7
#define NPTS (POOL * POOL)
#define CCH 256
#define LANES 16
#define ITEMS_PER_CTA 8
#define CTA_THREADS 128

__global__ void __launch_bounds__(CTA_THREADS, 16)
roi_fused_kernel(const float* __restrict__ boxes,
                 const float* __restrict__ image_shape,
                 const float* __restrict__ P2,
                 const float* __restrict__ P3,
                 const float* __restrict__ P4,
                 const float* __restrict__ P5,
                 float* __restrict__ out,
                 int total_items, int boxes_per_batch)
{
    __shared__ ulonglong4 s_addr[ITEMS_PER_CTA];
    __shared__ float4     s_w[ITEMS_PER_CTA];   // bilinear weights tl,tr,bl,br

    const int item_base = blockIdx.x * ITEMS_PER_CTA;
    const int tid = threadIdx.x;

    if (tid < ITEMS_PER_CTA) {
        const int item = item_base + tid;
        if (item < total_items) {
            const int bn = item / NPTS;
            const int pt = item - bn * NPTS;
            const int py = pt / POOL;
            const int px = pt - py * POOL;
            const int b  = bn / boxes_per_batch;

            const float4 bx = ((const float4*)boxes)[bn];
            const float y1 = bx.x, x1 = bx.y, y2 = bx.z, x2 = bx.w;
            const float h = y2 - y1;
            const float w = x2 - x1;

            // Level selection — exact reference fp32 op order; rintf == jnp.round.
            const float area = image_shape[0] * image_shape[1];
            float lvlf = log2f(sqrtf(h * w) / (224.0f / sqrtf(area)));
            lvlf = fminf(5.0f, fmaxf(2.0f, 4.0f + rintf(lvlf)));
            const int lvl = (int)lvlf;

            const float* fmap;
            int H;
            if (lvl == 2)      { fmap = P2; H = 256; }
            else if (lvl == 3) { fmap = P3; H = 128; }
            else if (lvl == 4) { fmap = P4; H = 64;  }
            else               { fmap = P5; H = 32;  }
            const int W = H;

            // Reference order: in_y = (y1 + h*gy) * (H-1)
            const float gy = (float)py * (1.0f / 6.0f);
            const float gx = (float)px * (1.0f / 6.0f);
            const float in_y = (y1 + h * gy) * (float)(H - 1);
            const float in_x = (x1 + w * gx) * (float)(W - 1);

            const float y0f = floorf(in_y);
            const float x0f = floorf(in_x);
            const float wy = in_y - y0f;
            const float wx = in_x - x0f;

            int y0  = min(max((int)y0f, 0), H - 1);
            int y1i = min(y0 + 1, H - 1);
            int x0  = min(max((int)x0f, 0), W - 1);
            int x1i = min(x0 + 1, W - 1);

            const unsigned long long base =
                (unsigned long long)fmap + (unsigned long long)b * H * W * CCH * 4ull;
            const unsigned long long rowT = base + (unsigned long long)(y0  * W) * (CCH * 4ull);
            const unsigned long long rowB = base + (unsigned long long)(y1i * W) * (CCH * 4ull);

            ulonglong4 a;
            a.x = rowT + (unsigned long long)x0  * (CCH * 4ull);
            a.y = rowT + (unsigned long long)x1i * (CCH * 4ull);
            a.z = rowB + (unsigned long long)x0  * (CCH * 4ull);
            a.w = rowB + (unsigned long long)x1i * (CCH * 4ull);
            s_addr[tid] = a;

            // Bilinear weights (weight-form lerp; ~ulp-level diff vs reference)
            const float iwx = 1.0f - wx;
            const float iwy = 1.0f - wy;
            s_w[tid] = make_float4(iwx * iwy,   // tl
                                   wx  * iwy,   // tr
                                   iwx * wy,    // bl
                                   wx  * wy);   // br
        }
    }
    __syncthreads();

    const int local = tid >> 4;            // item within CTA (0..7)
    const int lane  = tid & (LANES - 1);   // float4 lane group
    const int item = item_base + local;
    if (item >= total_items) return;

    const ulonglong4 a = s_addr[local];    // SMEM broadcast
    const float4 wv = s_w[local];
    const float w0 = wv.x, w1 = wv.y, w2 = wv.z, w3 = wv.w;

    const float4* __restrict__ tl = (const float4*)a.x;
    const float4* __restrict__ tr = (const float4*)a.y;
    const float4* __restrict__ bl = (const float4*)a.z;
    const float4* __restrict__ br = (const float4*)a.w;
    float4* __restrict__ o = (float4*)(out + (size_t)item * CCH);

#pragma unroll
    for (int j = 0; j < 4; j++) {
        const int c = lane + j * LANES;
        const float4 vtl = tl[c];
        const float4 vtr = tr[c];
        const float4 vbl = bl[c];
        const float4 vbr = br[c];
        float4 r;
        r.x = fmaf(vtl.x, w0, fmaf(vtr.x, w1, fmaf(vbl.x, w2, vbr.x * w3)));
        r.y = fmaf(vtl.y, w0, fmaf(vtr.y, w1, fmaf(vbl.y, w2, vbr.y * w3)));
        r.z = fmaf(vtl.z, w0, fmaf(vtr.z, w1, fmaf(vbl.z, w2, vbr.z * w3)));
        r.w = fmaf(vtl.w, w0, fmaf(vtr.w, w1, fmaf(vbl.w, w2, vbr.w * w3)));
        __stcs(&o[c], r);
    }
}

extern "C" void kernel_launch(void* const* d_in, const int* in_sizes, int n_in,
                              void* d_out, int out_size)
{
    const float* boxes = (const float*)d_in[0];
    const float* ishp  = (const float*)d_in[1];
    const float* P2    = (const float*)d_in[2];
    const float* P3    = (const float*)d_in[3];
    const float* P4    = (const float*)d_in[4];
    const float* P5    = (const float*)d_in[5];
    float* out = (float*)d_out;

    const int B = in_sizes[2] / (256 * 256 * 256);
    const int total_boxes = in_sizes[0] / 4;
    const int boxes_per_batch = total_boxes / B;
    const int total_items = total_boxes * NPTS;

    const int blocks = (total_items + ITEMS_PER_CTA - 1) / ITEMS_PER_CTA;
    roi_fused_kernel<<<blocks, CTA_THREADS>>>(boxes, ishp, P2, P3, P4, P5, out,
                                              total_items, boxes_per_batch);
}

// round 17
// speedup vs baseline: 1.0611x; 1.0611x over previous
#include <cuda_runtime.h>

// PyramidROIAlign: B=2, N=1000 boxes, C=256, 7x7 pool. Single fused kernel.
// CHAMPION (R12): 128-thread CTA = 8 items. Threads 0..7 compute per-item
// params into SMEM; barrier; all threads run the gather body (16 lanes/item,
// unroll-4 epochs, reference-form lerp). launch_bounds pins regs<=32
// (2048 thr/SM); __stcs keeps the 98MB write stream out of L2's way.
// Kernel runs at ~3.2TB/s HBM == the DRAM write-bandwidth ceiling for the
// 98MB output; measured floor across 8 structural variants.

#define POOL 7
#define NPTS (POOL * POOL)
#define CCH 256
#define LANES 16
#define ITEMS_PER_CTA 8
#define CTA_THREADS 128

__global__ void __launch_bounds__(CTA_THREADS, 16)
roi_fused_kernel(const float* __restrict__ boxes,
                 const float* __restrict__ image_shape,
                 const float* __restrict__ P2,
                 const float* __restrict__ P3,
                 const float* __restrict__ P4,
                 const float* __restrict__ P5,
                 float* __restrict__ out,
                 int total_items, int boxes_per_batch)
{
    __shared__ ulonglong4 s_addr[ITEMS_PER_CTA];
    __shared__ float2     s_w[ITEMS_PER_CTA];

    const int item_base = blockIdx.x * ITEMS_PER_CTA;
    const int tid = threadIdx.x;

    if (tid < ITEMS_PER_CTA) {
        const int item = item_base + tid;
        if (item < total_items) {
            const int bn = item / NPTS;
            const int pt = item - bn * NPTS;
            const int py = pt / POOL;
            const int px = pt - py * POOL;
            const int b  = bn / boxes_per_batch;

            const float4 bx = ((const float4*)boxes)[bn];
            const float y1 = bx.x, x1 = bx.y, y2 = bx.z, x2 = bx.w;
            const float h = y2 - y1;
            const float w = x2 - x1;

            // Level selection — exact reference fp32 op order; rintf == jnp.round.
            const float area = image_shape[0] * image_shape[1];
            float lvlf = log2f(sqrtf(h * w) / (224.0f / sqrtf(area)));
            lvlf = fminf(5.0f, fmaxf(2.0f, 4.0f + rintf(lvlf)));
            const int lvl = (int)lvlf;

            const float* fmap;
            int H;
            if (lvl == 2)      { fmap = P2; H = 256; }
            else if (lvl == 3) { fmap = P3; H = 128; }
            else if (lvl == 4) { fmap = P4; H = 64;  }
            else               { fmap = P5; H = 32;  }
            const int W = H;

            // Reference order: in_y = (y1 + h*gy) * (H-1)
            const float gy = (float)py * (1.0f / 6.0f);
            const float gx = (float)px * (1.0f / 6.0f);
            const float in_y = (y1 + h * gy) * (float)(H - 1);
            const float in_x = (x1 + w * gx) * (float)(W - 1);

            const float y0f = floorf(in_y);
            const float x0f = floorf(in_x);
            const float wy = in_y - y0f;
            const float wx = in_x - x0f;

            int y0  = min(max((int)y0f, 0), H - 1);
            int y1i = min(y0 + 1, H - 1);
            int x0  = min(max((int)x0f, 0), W - 1);
            int x1i = min(x0 + 1, W - 1);

            const unsigned long long base =
                (unsigned long long)fmap + (unsigned long long)b * H * W * CCH * 4ull;
            const unsigned long long rowT = base + (unsigned long long)(y0  * W) * (CCH * 4ull);
            const unsigned long long rowB = base + (unsigned long long)(y1i * W) * (CCH * 4ull);

            ulonglong4 a;
            a.x = rowT + (unsigned long long)x0  * (CCH * 4ull);
            a.y = rowT + (unsigned long long)x1i * (CCH * 4ull);
            a.z = rowB + (unsigned long long)x0  * (CCH * 4ull);
            a.w = rowB + (unsigned long long)x1i * (CCH * 4ull);
            s_addr[tid] = a;
            s_w[tid] = make_float2(wx, wy);
        }
    }
    __syncthreads();

    const int local = tid >> 4;            // item within CTA (0..7)
    const int lane  = tid & (LANES - 1);   // float4 lane group
    const int item = item_base + local;
    if (item >= total_items) return;

    const ulonglong4 a = s_addr[local];    // SMEM broadcast
    const float2 wv = s_w[local];
    const float wx = wv.x, wy = wv.y;

    const float4* __restrict__ tl = (const float4*)a.x;
    const float4* __restrict__ tr = (const float4*)a.y;
    const float4* __restrict__ bl = (const float4*)a.z;
    const float4* __restrict__ br = (const float4*)a.w;
    float4* __restrict__ o = (float4*)(out + (size_t)item * CCH);

#pragma unroll
    for (int j = 0; j < 4; j++) {
        const int c = lane + j * LANES;
        const float4 vtl = tl[c];
        const float4 vtr = tr[c];
        const float4 vbl = bl[c];
        const float4 vbr = br[c];
        float4 r;
        float t, bt;
        t  = vtl.x + (vtr.x - vtl.x) * wx;  bt = vbl.x + (vbr.x - vbl.x) * wx;  r.x = t + (bt - t) * wy;
        t  = vtl.y + (vtr.y - vtl.y) * wx;  bt = vbl.y + (vbr.y - vbl.y) * wx;  r.y = t + (bt - t) * wy;
        t  = vtl.z + (vtr.z - vtl.z) * wx;  bt = vbl.z + (vbr.z - vbl.z) * wx;  r.z = t + (bt - t) * wy;
        t  = vtl.w + (vtr.w - vtl.w) * wx;  bt = vbl.w + (vbr.w - vbl.w) * wx;  r.w = t + (bt - t) * wy;
        __stcs(&o[c], r);
    }
}

extern "C" void kernel_launch(void* const* d_in, const int* in_sizes, int n_in,
                              void* d_out, int out_size)
{
    const float* boxes = (const float*)d_in[0];
    const float* ishp  = (const float*)d_in[1];
    const float* P2    = (const float*)d_in[2];
    const float* P3    = (const float*)d_in[3];
    const float* P4    = (const float*)d_in[4];
    const float* P5    = (const float*)d_in[5];
    float* out = (float*)d_out;

    const int B = in_sizes[2] / (256 * 256 * 256);
    const int total_boxes = in_sizes[0] / 4;
    const int boxes_per_batch = total_boxes / B;
    const int total_items = total_boxes * NPTS;

    const int blocks = (total_items + ITEMS_PER_CTA - 1) / ITEMS_PER_CTA;
    roi_fused_kernel<<<blocks, CTA_THREADS>>>(boxes, ishp, P2, P3, P4, P5, out,
                                              total_items, boxes_per_batch);
}